// round 2
// baseline (speedup 1.0000x reference)
#include <cuda_runtime.h>
#include <math.h>

#define Nn    20000
#define Cc    128
#define Ff    512        // HEADS*NHID
#define Ee    320000
#define ET    340000     // E + N self loops
#define XSTR  640        // (NLAYERS+1)*Cc
#define NCLS  40

// ---------------- scratch (no dynamic allocation allowed) ----------------
__device__ float g_h[(size_t)Nn * Ff];     // h = X @ W  [N, 512]
__device__ float g_as[Nn * 4];             // a_src per node per head
__device__ float g_ad[Nn * 4];             // a_dst per node per head
__device__ int   g_rowptr[Nn + 1];
__device__ int   g_fill[Nn];
__device__ int   g_cnt[Nn];
__device__ int   g_col[ET];

// ---------------- init: X_all[:,0]=x, Y_all[:,0]=x, zero counts ----------
__global__ void init_kernel(const float* __restrict__ x,
                            float* __restrict__ Xall, float* __restrict__ Yall)
{
    int i = blockIdx.x * blockDim.x + threadIdx.x;
    if (i < Nn * Cc) {
        int n = i >> 7, c = i & 127;
        float v = x[i];
        Xall[(size_t)n * XSTR + c] = v;
        Yall[(size_t)n * XSTR + c] = v;
    }
    if (i < Nn) g_cnt[i] = 0;
}

// ---------------- CSR build (by dst, self-loops appended) ----------------
__global__ void count_kernel(const int* __restrict__ dst)
{
    int i = blockIdx.x * blockDim.x + threadIdx.x;
    if (i < ET) {
        int d = (i < Ee) ? dst[i] : (i - Ee);
        atomicAdd(&g_cnt[d], 1);
    }
}

__global__ void scan_kernel()
{
    __shared__ int wsum[32];
    __shared__ int carry_s;
    const int tid = threadIdx.x, lane = tid & 31, wp = tid >> 5;
    if (tid == 0) { carry_s = 0; g_rowptr[0] = 0; }
    __syncthreads();
    for (int base = 0; base < Nn; base += 1024) {
        int idx = base + tid;
        int v = (idx < Nn) ? g_cnt[idx] : 0;
        int x = v;
        #pragma unroll
        for (int o = 1; o < 32; o <<= 1) {
            int t = __shfl_up_sync(0xffffffffu, x, o);
            if (lane >= o) x += t;
        }
        if (lane == 31) wsum[wp] = x;
        __syncthreads();
        if (wp == 0) {
            int y = wsum[lane];
            #pragma unroll
            for (int o = 1; o < 32; o <<= 1) {
                int t = __shfl_up_sync(0xffffffffu, y, o);
                if (lane >= o) y += t;
            }
            wsum[lane] = y;
        }
        __syncthreads();
        int incl = x + (wp ? wsum[wp - 1] : 0) + carry_s;
        if (idx < Nn) {
            g_rowptr[idx + 1] = incl;
            g_fill[idx] = incl - v;      // exclusive prefix = write cursor
        }
        __syncthreads();
        if (tid == 1023) carry_s = incl;
        __syncthreads();
    }
}

__global__ void fill_kernel(const int* __restrict__ src, const int* __restrict__ dst)
{
    int i = blockIdx.x * blockDim.x + threadIdx.x;
    if (i < ET) {
        int s, d;
        if (i < Ee) { s = src[i]; d = dst[i]; }
        else        { s = d = i - Ee; }
        int p = atomicAdd(&g_fill[d], 1);
        g_col[p] = s;
    }
}

// ---------------- GEMM: h = X_l @ W  (M=20000, N=512, K=128) -------------
#define SMEM_GEMM ((128 * 132 + 128 * 128) * 4)
extern __shared__ float gsm[];
__global__ __launch_bounds__(256) void gemm_kernel(const float* __restrict__ Xall,
                                                   int loff,
                                                   const float* __restrict__ W)
{
    float* As = gsm;               // [128 rows][132 pad]   (m-major)
    float* Bs = gsm + 128 * 132;   // [128 k][128 n]        (k-major)
    const int tid = threadIdx.x;
    const int bm = blockIdx.x * 128;
    const int bn = blockIdx.y * 128;

    for (int f = tid; f < 4096; f += 256) {
        int row = f >> 5, k4 = (f & 31) << 2;
        float4 v = make_float4(0.f, 0.f, 0.f, 0.f);
        int gr = bm + row;
        if (gr < Nn) v = *(const float4*)(Xall + (size_t)gr * XSTR + loff + k4);
        *(float4*)(As + row * 132 + k4) = v;
    }
    for (int f = tid; f < 4096; f += 256) {
        int k = f >> 5, n4 = (f & 31) << 2;
        *(float4*)(Bs + k * 128 + n4) = *(const float4*)(W + (size_t)k * Ff + bn + n4);
    }
    __syncthreads();

    const int tx = tid & 15, ty = tid >> 4;
    const int m0 = ty * 8, n0 = tx * 8;
    float acc[8][8];
    #pragma unroll
    for (int i = 0; i < 8; i++)
        #pragma unroll
        for (int j = 0; j < 8; j++) acc[i][j] = 0.f;

    #pragma unroll 8
    for (int k = 0; k < 128; k++) {
        float a[8], b[8];
        #pragma unroll
        for (int i = 0; i < 8; i++) a[i] = As[(m0 + i) * 132 + k];
        float4 b0 = *(const float4*)(Bs + k * 128 + n0);
        float4 b1 = *(const float4*)(Bs + k * 128 + n0 + 4);
        b[0] = b0.x; b[1] = b0.y; b[2] = b0.z; b[3] = b0.w;
        b[4] = b1.x; b[5] = b1.y; b[6] = b1.z; b[7] = b1.w;
        #pragma unroll
        for (int i = 0; i < 8; i++)
            #pragma unroll
            for (int j = 0; j < 8; j++) acc[i][j] = fmaf(a[i], b[j], acc[i][j]);
    }
    #pragma unroll
    for (int i = 0; i < 8; i++) {
        int gr = bm + m0 + i;
        if (gr < Nn) {
            float4 v0 = make_float4(acc[i][0], acc[i][1], acc[i][2], acc[i][3]);
            float4 v1 = make_float4(acc[i][4], acc[i][5], acc[i][6], acc[i][7]);
            *(float4*)(g_h + (size_t)gr * Ff + bn + n0)     = v0;
            *(float4*)(g_h + (size_t)gr * Ff + bn + n0 + 4) = v1;
        }
    }
}

// ---------------- attention coefficients a_s, a_d ------------------------
__global__ __launch_bounds__(128) void attn_kernel(const float* __restrict__ att_s,
                                                   const float* __restrict__ att_d)
{
    const int n = blockIdx.x;
    const int c = threadIdx.x, lane = c & 31, wp = c >> 5;
    const float* hp = g_h + (size_t)n * Ff;
    float sv[4], dv[4];
    #pragma unroll
    for (int h = 0; h < 4; h++) {
        float v = hp[h * Cc + c];
        sv[h] = v * att_s[h * Cc + c];
        dv[h] = v * att_d[h * Cc + c];
    }
    #pragma unroll
    for (int h = 0; h < 4; h++)
        #pragma unroll
        for (int o = 16; o; o >>= 1) {
            sv[h] += __shfl_xor_sync(0xffffffffu, sv[h], o);
            dv[h] += __shfl_xor_sync(0xffffffffu, dv[h], o);
        }
    __shared__ float ss[4][4], sd[4][4];
    if (lane == 0) {
        #pragma unroll
        for (int h = 0; h < 4; h++) { ss[h][wp] = sv[h]; sd[h][wp] = dv[h]; }
    }
    __syncthreads();
    if (c < 4) {
        g_as[n * 4 + c] = ss[c][0] + ss[c][1] + ss[c][2] + ss[c][3];
        g_ad[n * 4 + c] = sd[c][0] + sd[c][1] + sd[c][2] + sd[c][3];
    }
}

// ---------------- edge phase: softmax + aggregate + GraphCON update ------
// one 128-thread block per dst node; thread t owns flat channels 4t..4t+3
// (all in head t>>5), which are exactly the channels averaged into agg[t].
__global__ __launch_bounds__(128) void edge_kernel(const float* __restrict__ bias,
                                                   float* __restrict__ Xall,
                                                   float* __restrict__ Yall, int l)
{
    const int d = blockIdx.x;
    const int tid = threadIdx.x;
    const int lane = tid & 31, wp = tid >> 5;
    const int r0 = g_rowptr[d];
    const int deg = g_rowptr[d + 1] - r0;
    const float4 ad = *(const float4*)(g_ad + d * 4);

    __shared__ float4 red[4];
    __shared__ int    s_s[128];
    __shared__ float4 s_w[128];

    // pass 1: per-head max of leaky_relu(a_s[s]+a_d[d])
    float m0 = -1e30f, m1 = -1e30f, m2 = -1e30f, m3 = -1e30f;
    for (int i = tid; i < deg; i += 128) {
        int s = g_col[r0 + i];
        float4 as = *(const float4*)(g_as + s * 4);
        float e0 = as.x + ad.x; e0 = fmaxf(e0, 0.2f * e0);
        float e1 = as.y + ad.y; e1 = fmaxf(e1, 0.2f * e1);
        float e2 = as.z + ad.z; e2 = fmaxf(e2, 0.2f * e2);
        float e3 = as.w + ad.w; e3 = fmaxf(e3, 0.2f * e3);
        m0 = fmaxf(m0, e0); m1 = fmaxf(m1, e1);
        m2 = fmaxf(m2, e2); m3 = fmaxf(m3, e3);
    }
    #pragma unroll
    for (int o = 16; o; o >>= 1) {
        m0 = fmaxf(m0, __shfl_xor_sync(0xffffffffu, m0, o));
        m1 = fmaxf(m1, __shfl_xor_sync(0xffffffffu, m1, o));
        m2 = fmaxf(m2, __shfl_xor_sync(0xffffffffu, m2, o));
        m3 = fmaxf(m3, __shfl_xor_sync(0xffffffffu, m3, o));
    }
    if (lane == 0) red[wp] = make_float4(m0, m1, m2, m3);
    __syncthreads();
    float4 M;
    M.x = fmaxf(fmaxf(red[0].x, red[1].x), fmaxf(red[2].x, red[3].x));
    M.y = fmaxf(fmaxf(red[0].y, red[1].y), fmaxf(red[2].y, red[3].y));
    M.z = fmaxf(fmaxf(red[0].z, red[1].z), fmaxf(red[2].z, red[3].z));
    M.w = fmaxf(fmaxf(red[0].w, red[1].w), fmaxf(red[2].w, red[3].w));
    __syncthreads();

    // pass 2: per-head sum of exp(e - m)
    float s0 = 0.f, s1 = 0.f, s2 = 0.f, s3 = 0.f;
    for (int i = tid; i < deg; i += 128) {
        int s = g_col[r0 + i];
        float4 as = *(const float4*)(g_as + s * 4);
        float e0 = as.x + ad.x; e0 = fmaxf(e0, 0.2f * e0);
        float e1 = as.y + ad.y; e1 = fmaxf(e1, 0.2f * e1);
        float e2 = as.z + ad.z; e2 = fmaxf(e2, 0.2f * e2);
        float e3 = as.w + ad.w; e3 = fmaxf(e3, 0.2f * e3);
        s0 += expf(e0 - M.x); s1 += expf(e1 - M.y);
        s2 += expf(e2 - M.z); s3 += expf(e3 - M.w);
    }
    #pragma unroll
    for (int o = 16; o; o >>= 1) {
        s0 += __shfl_xor_sync(0xffffffffu, s0, o);
        s1 += __shfl_xor_sync(0xffffffffu, s1, o);
        s2 += __shfl_xor_sync(0xffffffffu, s2, o);
        s3 += __shfl_xor_sync(0xffffffffu, s3, o);
    }
    if (lane == 0) red[wp] = make_float4(s0, s1, s2, s3);
    __syncthreads();
    float4 R;
    R.x = 1.0f / (red[0].x + red[1].x + red[2].x + red[3].x);
    R.y = 1.0f / (red[0].y + red[1].y + red[2].y + red[3].y);
    R.z = 1.0f / (red[0].z + red[1].z + red[2].z + red[3].z);
    R.w = 1.0f / (red[0].w + red[1].w + red[2].w + red[3].w);
    __syncthreads();

    // pass 3: weighted aggregation, chunked through shared memory
    float4 acc = make_float4(0.f, 0.f, 0.f, 0.f);
    for (int base = 0; base < deg; base += 128) {
        int cnt = min(128, deg - base);
        if (tid < cnt) {
            int s = g_col[r0 + base + tid];
            float4 as = *(const float4*)(g_as + s * 4);
            float e0 = as.x + ad.x; e0 = fmaxf(e0, 0.2f * e0);
            float e1 = as.y + ad.y; e1 = fmaxf(e1, 0.2f * e1);
            float e2 = as.z + ad.z; e2 = fmaxf(e2, 0.2f * e2);
            float e3 = as.w + ad.w; e3 = fmaxf(e3, 0.2f * e3);
            s_s[tid] = s;
            s_w[tid] = make_float4(expf(e0 - M.x) * R.x, expf(e1 - M.y) * R.y,
                                   expf(e2 - M.z) * R.z, expf(e3 - M.w) * R.w);
        }
        __syncthreads();
        const float* wf = (const float*)s_w;
        #pragma unroll 4
        for (int i = 0; i < cnt; i++) {
            float w = wf[i * 4 + wp];
            const float4 hv = *(const float4*)(g_h + (size_t)s_s[i] * Ff + tid * 4);
            acc.x = fmaf(w, hv.x, acc.x);
            acc.y = fmaf(w, hv.y, acc.y);
            acc.z = fmaf(w, hv.z, acc.z);
            acc.w = fmaf(w, hv.w, acc.w);
        }
        __syncthreads();
    }

    // + bias, ELU, regroup-mean (flat 4t..4t+3 -> agg[t]), GraphCON update
    float4 b = *(const float4*)(bias + tid * 4);
    float v0 = acc.x + b.x; v0 = v0 > 0.f ? v0 : expm1f(v0);
    float v1 = acc.y + b.y; v1 = v1 > 0.f ? v1 : expm1f(v1);
    float v2 = acc.z + b.z; v2 = v2 > 0.f ? v2 : expm1f(v2);
    float v3 = acc.w + b.w; v3 = v3 > 0.f ? v3 : expm1f(v3);
    float agg = 0.25f * (v0 + v1 + v2 + v3);

    size_t ofs = (size_t)d * XSTR + (size_t)l * Cc + tid;
    float xold = Xall[ofs];
    Xall[ofs + Cc] = agg;            // X_{l+1} = agg
    Yall[ofs + Cc] = agg - xold;     // Y_{l+1} = agg - X_l
}

// ---------------- classifier: out = X4 @ Wr^T + br -----------------------
__global__ __launch_bounds__(64) void logits_kernel(const float* __restrict__ Xall,
                                                    const float* __restrict__ Wr,
                                                    const float* __restrict__ br,
                                                    float* __restrict__ out)
{
    __shared__ float Xs[32 * 132];
    __shared__ float Ws[40 * 132];
    __shared__ float bs[40];
    const int tid = threadIdx.x;
    const int bmn = blockIdx.x * 32;

    for (int f = tid; f < 32 * 32; f += 64) {
        int r = f >> 5, k4 = (f & 31) << 2;
        int g = bmn + r;
        float4 v = make_float4(0.f, 0.f, 0.f, 0.f);
        if (g < Nn) v = *(const float4*)(Xall + (size_t)g * XSTR + 4 * Cc + k4);
        *(float4*)(Xs + r * 132 + k4) = v;
    }
    for (int f = tid; f < 40 * 32; f += 64) {
        int r = f >> 5, k4 = (f & 31) << 2;
        *(float4*)(Ws + r * 132 + k4) = *(const float4*)(Wr + (size_t)r * Cc + k4);
    }
    if (tid < 40) bs[tid] = br[tid];
    __syncthreads();

    const int ty = tid >> 3, tx = tid & 7;   // 8x4 nodes, 8x5 classes
    float acc[4][5];
    #pragma unroll
    for (int i = 0; i < 4; i++)
        #pragma unroll
        for (int j = 0; j < 5; j++) acc[i][j] = 0.f;

    #pragma unroll 4
    for (int k = 0; k < 128; k++) {
        float a[4], b[5];
        #pragma unroll
        for (int i = 0; i < 4; i++) a[i] = Xs[(ty * 4 + i) * 132 + k];
        #pragma unroll
        for (int j = 0; j < 5; j++) b[j] = Ws[(tx * 5 + j) * 132 + k];
        #pragma unroll
        for (int i = 0; i < 4; i++)
            #pragma unroll
            for (int j = 0; j < 5; j++) acc[i][j] = fmaf(a[i], b[j], acc[i][j]);
    }
    #pragma unroll
    for (int i = 0; i < 4; i++) {
        int g = bmn + ty * 4 + i;
        if (g < Nn)
            #pragma unroll
            for (int j = 0; j < 5; j++)
                out[(size_t)g * NCLS + tx * 5 + j] = acc[i][j] + bs[tx * 5 + j];
    }
}

// ---------------- launch --------------------------------------------------
extern "C" void kernel_launch(void* const* d_in, const int* in_sizes, int n_in,
                              void* d_out, int out_size)
{
    const float* x     = (const float*)d_in[0];
    const int*   src   = (const int*)  d_in[1];
    const int*   dst   = (const int*)  d_in[2];
    const float* W     = (const float*)d_in[3];
    const float* att_s = (const float*)d_in[4];
    const float* att_d = (const float*)d_in[5];
    const float* bias  = (const float*)d_in[6];
    const float* Wr    = (const float*)d_in[7];
    const float* br    = (const float*)d_in[8];

    float* out  = (float*)d_out;
    float* Xall = out + (size_t)Nn * NCLS;            // [N, 5, 128]
    float* Yall = Xall + (size_t)Nn * 5 * Cc;         // [N, 5, 128]

    cudaFuncSetAttribute(gemm_kernel, cudaFuncAttributeMaxDynamicSharedMemorySize,
                         SMEM_GEMM);

    init_kernel<<<(Nn * Cc + 255) / 256, 256>>>(x, Xall, Yall);
    count_kernel<<<(ET + 255) / 256, 256>>>(dst);
    scan_kernel<<<1, 1024>>>();
    fill_kernel<<<(ET + 255) / 256, 256>>>(src, dst);

    for (int l = 0; l < 4; l++) {
        gemm_kernel<<<dim3(157, 4), 256, SMEM_GEMM>>>(Xall, l * Cc, W);
        attn_kernel<<<Nn, 128>>>(att_s, att_d);
        edge_kernel<<<Nn, 128>>>(bias, Xall, Yall, l);
    }
    logits_kernel<<<(Nn + 31) / 32, 64>>>(Xall, Wr, br, out);
}

// round 4
// speedup vs baseline: 1.4535x; 1.4535x over previous
#include <cuda_runtime.h>
#include <cuda_bf16.h>
#include <math.h>
#include <cstdint>

#define Nn    20000
#define Cc    128
#define Ff    512        // HEADS*NHID
#define Ee    320000
#define ET    340000     // E + N self loops
#define XSTR  640        // (NLAYERS+1)*Cc
#define NCLS  40

// ---------------- scratch (no dynamic allocation allowed) ----------------
__device__ float g_h[(size_t)Nn * Ff];     // h = X @ W  [N, 512]
__device__ float g_as[Nn * 4];             // a_src per node per head
__device__ float g_ad[Nn * 4];             // a_dst per node per head
__device__ int   g_rowptr[Nn + 1];
__device__ int   g_fill[Nn];
__device__ int   g_cnt[Nn];
__device__ int   g_col[ET];
__device__ __nv_bfloat16 g_WThi[Ff * Cc];  // W^T split hi  [n=512][k=128]
__device__ __nv_bfloat16 g_WTlo[Ff * Cc];  // W^T split lo

// ---------------- init ---------------------------------------------------
__global__ void init_kernel(const float* __restrict__ x,
                            float* __restrict__ Xall, float* __restrict__ Yall)
{
    int i = blockIdx.x * blockDim.x + threadIdx.x;
    if (i < Nn * Cc) {
        int n = i >> 7, c = i & 127;
        float v = x[i];
        Xall[(size_t)n * XSTR + c] = v;
        Yall[(size_t)n * XSTR + c] = v;
    }
    if (i < Nn) g_cnt[i] = 0;
}

// ---------------- one-time W transpose + bf16 split ----------------------
__global__ void split_w_kernel(const float* __restrict__ W)
{
    int i = blockIdx.x * blockDim.x + threadIdx.x;
    if (i < Cc * Ff) {
        int k = i >> 9, n = i & 511;
        float w = W[i];
        __nv_bfloat16 hi = __float2bfloat16(w);
        __nv_bfloat16 lo = __float2bfloat16(w - __bfloat162float(hi));
        g_WThi[n * Cc + k] = hi;
        g_WTlo[n * Cc + k] = lo;
    }
}

// ---------------- CSR build (by dst, self-loops appended) ----------------
__global__ void count_kernel(const int* __restrict__ dst)
{
    int i = blockIdx.x * blockDim.x + threadIdx.x;
    if (i < ET) {
        int d = (i < Ee) ? dst[i] : (i - Ee);
        atomicAdd(&g_cnt[d], 1);
    }
}

__global__ void scan_kernel()
{
    __shared__ int wsum[32];
    __shared__ int carry_s;
    const int tid = threadIdx.x, lane = tid & 31, wp = tid >> 5;
    if (tid == 0) { carry_s = 0; g_rowptr[0] = 0; }
    __syncthreads();
    for (int base = 0; base < Nn; base += 1024) {
        int idx = base + tid;
        int v = (idx < Nn) ? g_cnt[idx] : 0;
        int x = v;
        #pragma unroll
        for (int o = 1; o < 32; o <<= 1) {
            int t = __shfl_up_sync(0xffffffffu, x, o);
            if (lane >= o) x += t;
        }
        if (lane == 31) wsum[wp] = x;
        __syncthreads();
        if (wp == 0) {
            int y = wsum[lane];
            #pragma unroll
            for (int o = 1; o < 32; o <<= 1) {
                int t = __shfl_up_sync(0xffffffffu, y, o);
                if (lane >= o) y += t;
            }
            wsum[lane] = y;
        }
        __syncthreads();
        int incl = x + (wp ? wsum[wp - 1] : 0) + carry_s;
        if (idx < Nn) {
            g_rowptr[idx + 1] = incl;
            g_fill[idx] = incl - v;
        }
        __syncthreads();
        if (tid == 1023) carry_s = incl;
        __syncthreads();
    }
}

__global__ void fill_kernel(const int* __restrict__ src, const int* __restrict__ dst)
{
    int i = blockIdx.x * blockDim.x + threadIdx.x;
    if (i < ET) {
        int s, d;
        if (i < Ee) { s = src[i]; d = dst[i]; }
        else        { s = d = i - Ee; }
        int p = atomicAdd(&g_fill[d], 1);
        g_col[p] = s;
    }
}

// ---------------- bf16 split helper --------------------------------------
__device__ __forceinline__ void split2(float a0, float a1, uint32_t& hi, uint32_t& lo) {
    __nv_bfloat16 h0 = __float2bfloat16(a0);
    __nv_bfloat16 h1 = __float2bfloat16(a1);
    __nv_bfloat16 l0 = __float2bfloat16(a0 - __bfloat162float(h0));
    __nv_bfloat16 l1 = __float2bfloat16(a1 - __bfloat162float(h1));
    hi = (uint32_t)__bfloat16_as_ushort(h0) | ((uint32_t)__bfloat16_as_ushort(h1) << 16);
    lo = (uint32_t)__bfloat16_as_ushort(l0) | ((uint32_t)__bfloat16_as_ushort(l1) << 16);
}

__device__ __forceinline__ void mma16816(float* c, const uint32_t* a, const uint32_t* b) {
    asm volatile("mma.sync.aligned.m16n8k16.row.col.f32.bf16.bf16.f32 "
        "{%0,%1,%2,%3}, {%4,%5,%6,%7}, {%8,%9}, {%0,%1,%2,%3};"
        : "+f"(c[0]), "+f"(c[1]), "+f"(c[2]), "+f"(c[3])
        : "r"(a[0]), "r"(a[1]), "r"(a[2]), "r"(a[3]), "r"(b[0]), "r"(b[1]));
}

// ---------------- mma.sync GEMM + fused attention coefficients -----------
// One CTA = 128 rows, loops over 4 n-tiles of 128 cols (whole Ff=512).
// bf16x3: h = Ahi*Bhi + Ahi*Blo + Alo*Bhi (fp32 accumulate).
// SMEM byte layout (dynamic):
#define SM_AHI  0
#define SM_ALO  34816      // 128 rows * 272B
#define SM_BHI  69632
#define SM_BLO  104448
#define SM_ATTS 139264     // 512 floats
#define SM_ATTD 141312     // 512 floats
#define SM_AS   143360     // 512 floats (128 rows x 4 heads)
#define SM_AD   145408     // 512 floats
#define SMEM_MG 147456

__global__ __launch_bounds__(256, 1) void mma_gemm_kernel(
    const float* __restrict__ Xall, int loff,
    const float* __restrict__ att_s, const float* __restrict__ att_d)
{
    extern __shared__ __align__(16) char smem[];
    const int tid = threadIdx.x;
    const int wid = tid >> 5, lane = tid & 31;
    const int g = lane >> 2, q = lane & 3;
    const int wm = wid & 1, wn = wid >> 1;       // 2 x 4 warp grid
    const int bm = blockIdx.x * 128;

    float* s_atts = (float*)(smem + SM_ATTS);
    float* s_attd = (float*)(smem + SM_ATTD);
    float* s_as   = (float*)(smem + SM_AS);
    float* s_ad   = (float*)(smem + SM_AD);

    // att vectors + zero attention accumulators
    for (int i = tid; i < 512; i += 256) {
        s_atts[i] = att_s[i];
        s_attd[i] = att_d[i];
        s_as[i] = 0.f;
        s_ad[i] = 0.f;
    }

    // ---- load + split A tile (128 rows x 128 k), stride 272B, hi/lo ----
    #pragma unroll
    for (int it = 0; it < 8; it++) {
        int idx = it * 256 + tid;        // 0..2047
        int r   = idx >> 4;              // row 0..127
        int kg  = idx & 15;              // 8-elem group
        int gm  = bm + r;
        float v[8];
        if (gm < Nn) {
            const float* p = Xall + (size_t)gm * XSTR + loff + kg * 8;
            float4 u0 = *(const float4*)p;
            float4 u1 = *(const float4*)(p + 4);
            v[0]=u0.x; v[1]=u0.y; v[2]=u0.z; v[3]=u0.w;
            v[4]=u1.x; v[5]=u1.y; v[6]=u1.z; v[7]=u1.w;
        } else {
            #pragma unroll
            for (int j = 0; j < 8; j++) v[j] = 0.f;
        }
        uint32_t hi[4], lo[4];
        #pragma unroll
        for (int j = 0; j < 4; j++) split2(v[2*j], v[2*j+1], hi[j], lo[j]);
        uint32_t off = (uint32_t)(r * 272 + kg * 16);
        *(uint4*)(smem + SM_AHI + off) = make_uint4(hi[0], hi[1], hi[2], hi[3]);
        *(uint4*)(smem + SM_ALO + off) = make_uint4(lo[0], lo[1], lo[2], lo[3]);
    }

    // per-thread fragment base offsets (bytes)
    const int a_base = (wm * 64 + g) * 272 + q * 4;
    const int b_base = (wn * 32 + g) * 272 + q * 4;

    float acc[4][4][4];

    for (int nt = 0; nt < 4; nt++) {
        // ---- copy B tile (128 n-rows x 128 k bf16, hi+lo) ----
        const int bn = nt * 128;
        #pragma unroll
        for (int it = 0; it < 8; it++) {
            int idx = it * 256 + tid;
            int r = idx >> 4, kg = idx & 15;
            uint32_t off = (uint32_t)(r * 272 + kg * 16);
            *(uint4*)(smem + SM_BHI + off) =
                *(const uint4*)((const char*)g_WThi + ((size_t)(bn + r) * Cc + kg * 8) * 2);
            *(uint4*)(smem + SM_BLO + off) =
                *(const uint4*)((const char*)g_WTlo + ((size_t)(bn + r) * Cc + kg * 8) * 2);
        }
        __syncthreads();

        #pragma unroll
        for (int mf = 0; mf < 4; mf++)
            #pragma unroll
            for (int nf = 0; nf < 4; nf++)
                #pragma unroll
                for (int j = 0; j < 4; j++) acc[mf][nf][j] = 0.f;

        // ---- K loop: 8 steps of k16 ----
        #pragma unroll
        for (int ks = 0; ks < 8; ks++) {
            uint32_t bh[4][2], bl[4][2];
            #pragma unroll
            for (int nf = 0; nf < 4; nf++) {
                int bo = b_base + nf * 8 * 272 + ks * 32;
                bh[nf][0] = *(const uint32_t*)(smem + SM_BHI + bo);
                bh[nf][1] = *(const uint32_t*)(smem + SM_BHI + bo + 16);
                bl[nf][0] = *(const uint32_t*)(smem + SM_BLO + bo);
                bl[nf][1] = *(const uint32_t*)(smem + SM_BLO + bo + 16);
            }
            #pragma unroll
            for (int mf = 0; mf < 4; mf++) {
                int ao = a_base + mf * 16 * 272 + ks * 32;
                uint32_t ah[4], al[4];
                ah[0] = *(const uint32_t*)(smem + SM_AHI + ao);
                ah[1] = *(const uint32_t*)(smem + SM_AHI + ao + 2176);
                ah[2] = *(const uint32_t*)(smem + SM_AHI + ao + 16);
                ah[3] = *(const uint32_t*)(smem + SM_AHI + ao + 2176 + 16);
                al[0] = *(const uint32_t*)(smem + SM_ALO + ao);
                al[1] = *(const uint32_t*)(smem + SM_ALO + ao + 2176);
                al[2] = *(const uint32_t*)(smem + SM_ALO + ao + 16);
                al[3] = *(const uint32_t*)(smem + SM_ALO + ao + 2176 + 16);
                #pragma unroll
                for (int nf = 0; nf < 4; nf++) {
                    mma16816(acc[mf][nf], ah, bh[nf]);
                    mma16816(acc[mf][nf], ah, bl[nf]);
                    mma16816(acc[mf][nf], al, bh[nf]);
                }
            }
        }

        // ---- epilogue: write h, accumulate attention dots ----
        #pragma unroll
        for (int mf = 0; mf < 4; mf++) {
            #pragma unroll
            for (int i = 0; i < 2; i++) {
                int row = wm * 64 + mf * 16 + i * 8 + g;
                int gm  = bm + row;
                float as_p = 0.f, ad_p = 0.f;
                #pragma unroll
                for (int nf = 0; nf < 4; nf++) {
                    float c0 = acc[mf][nf][i * 2];
                    float c1 = acc[mf][nf][i * 2 + 1];
                    int col = nt * 128 + wn * 32 + nf * 8 + q * 2;
                    if (gm < Nn)
                        *(float2*)(g_h + (size_t)gm * Ff + col) = make_float2(c0, c1);
                    as_p += c0 * s_atts[col] + c1 * s_atts[col + 1];
                    ad_p += c0 * s_attd[col] + c1 * s_attd[col + 1];
                }
                as_p += __shfl_xor_sync(0xffffffffu, as_p, 1);
                as_p += __shfl_xor_sync(0xffffffffu, as_p, 2);
                ad_p += __shfl_xor_sync(0xffffffffu, ad_p, 1);
                ad_p += __shfl_xor_sync(0xffffffffu, ad_p, 2);
                if (q == 0) {
                    atomicAdd(&s_as[row * 4 + nt], as_p);   // head == nt
                    atomicAdd(&s_ad[row * 4 + nt], ad_p);
                }
            }
        }
        __syncthreads();
    }

    // ---- write attention coefficients ----
    for (int i = tid; i < 512; i += 256) {
        int row = i >> 2;
        int gm = bm + row;
        if (gm < Nn) {
            g_as[gm * 4 + (i & 3)] = s_as[i];
            g_ad[gm * 4 + (i & 3)] = s_ad[i];
        }
    }
}

// ---------------- edge phase: softmax + aggregate + GraphCON update ------
__global__ __launch_bounds__(128) void edge_kernel(const float* __restrict__ bias,
                                                   float* __restrict__ Xall,
                                                   float* __restrict__ Yall, int l)
{
    const int d = blockIdx.x;
    const int tid = threadIdx.x;
    const int lane = tid & 31, wp = tid >> 5;
    const int r0 = g_rowptr[d];
    const int deg = g_rowptr[d + 1] - r0;
    const float4 ad = *(const float4*)(g_ad + d * 4);

    __shared__ float4 red[4];
    __shared__ int    s_s[128];
    __shared__ float4 s_w[128];

    // pass 1: per-head max of leaky_relu(a_s[s]+a_d[d])
    float m0 = -1e30f, m1 = -1e30f, m2 = -1e30f, m3 = -1e30f;
    for (int i = tid; i < deg; i += 128) {
        int s = g_col[r0 + i];
        float4 as = *(const float4*)(g_as + s * 4);
        float e0 = as.x + ad.x; e0 = fmaxf(e0, 0.2f * e0);
        float e1 = as.y + ad.y; e1 = fmaxf(e1, 0.2f * e1);
        float e2 = as.z + ad.z; e2 = fmaxf(e2, 0.2f * e2);
        float e3 = as.w + ad.w; e3 = fmaxf(e3, 0.2f * e3);
        m0 = fmaxf(m0, e0); m1 = fmaxf(m1, e1);
        m2 = fmaxf(m2, e2); m3 = fmaxf(m3, e3);
    }
    #pragma unroll
    for (int o = 16; o; o >>= 1) {
        m0 = fmaxf(m0, __shfl_xor_sync(0xffffffffu, m0, o));
        m1 = fmaxf(m1, __shfl_xor_sync(0xffffffffu, m1, o));
        m2 = fmaxf(m2, __shfl_xor_sync(0xffffffffu, m2, o));
        m3 = fmaxf(m3, __shfl_xor_sync(0xffffffffu, m3, o));
    }
    if (lane == 0) red[wp] = make_float4(m0, m1, m2, m3);
    __syncthreads();
    float4 M;
    M.x = fmaxf(fmaxf(red[0].x, red[1].x), fmaxf(red[2].x, red[3].x));
    M.y = fmaxf(fmaxf(red[0].y, red[1].y), fmaxf(red[2].y, red[3].y));
    M.z = fmaxf(fmaxf(red[0].z, red[1].z), fmaxf(red[2].z, red[3].z));
    M.w = fmaxf(fmaxf(red[0].w, red[1].w), fmaxf(red[2].w, red[3].w));
    __syncthreads();

    // pass 2: per-head sum of exp(e - m)
    float s0 = 0.f, s1 = 0.f, s2 = 0.f, s3 = 0.f;
    for (int i = tid; i < deg; i += 128) {
        int s = g_col[r0 + i];
        float4 as = *(const float4*)(g_as + s * 4);
        float e0 = as.x + ad.x; e0 = fmaxf(e0, 0.2f * e0);
        float e1 = as.y + ad.y; e1 = fmaxf(e1, 0.2f * e1);
        float e2 = as.z + ad.z; e2 = fmaxf(e2, 0.2f * e2);
        float e3 = as.w + ad.w; e3 = fmaxf(e3, 0.2f * e3);
        s0 += expf(e0 - M.x); s1 += expf(e1 - M.y);
        s2 += expf(e2 - M.z); s3 += expf(e3 - M.w);
    }
    #pragma unroll
    for (int o = 16; o; o >>= 1) {
        s0 += __shfl_xor_sync(0xffffffffu, s0, o);
        s1 += __shfl_xor_sync(0xffffffffu, s1, o);
        s2 += __shfl_xor_sync(0xffffffffu, s2, o);
        s3 += __shfl_xor_sync(0xffffffffu, s3, o);
    }
    if (lane == 0) red[wp] = make_float4(s0, s1, s2, s3);
    __syncthreads();
    float4 R;
    R.x = 1.0f / (red[0].x + red[1].x + red[2].x + red[3].x);
    R.y = 1.0f / (red[0].y + red[1].y + red[2].y + red[3].y);
    R.z = 1.0f / (red[0].z + red[1].z + red[2].z + red[3].z);
    R.w = 1.0f / (red[0].w + red[1].w + red[2].w + red[3].w);
    __syncthreads();

    // pass 3: weighted aggregation, chunked through shared memory
    float4 acc = make_float4(0.f, 0.f, 0.f, 0.f);
    for (int base = 0; base < deg; base += 128) {
        int cnt = min(128, deg - base);
        if (tid < cnt) {
            int s = g_col[r0 + base + tid];
            float4 as = *(const float4*)(g_as + s * 4);
            float e0 = as.x + ad.x; e0 = fmaxf(e0, 0.2f * e0);
            float e1 = as.y + ad.y; e1 = fmaxf(e1, 0.2f * e1);
            float e2 = as.z + ad.z; e2 = fmaxf(e2, 0.2f * e2);
            float e3 = as.w + ad.w; e3 = fmaxf(e3, 0.2f * e3);
            s_s[tid] = s;
            s_w[tid] = make_float4(expf(e0 - M.x) * R.x, expf(e1 - M.y) * R.y,
                                   expf(e2 - M.z) * R.z, expf(e3 - M.w) * R.w);
        }
        __syncthreads();
        const float* wf = (const float*)s_w;
        #pragma unroll 4
        for (int i = 0; i < cnt; i++) {
            float w = wf[i * 4 + wp];
            const float4 hv = *(const float4*)(g_h + (size_t)s_s[i] * Ff + tid * 4);
            acc.x = fmaf(w, hv.x, acc.x);
            acc.y = fmaf(w, hv.y, acc.y);
            acc.z = fmaf(w, hv.z, acc.z);
            acc.w = fmaf(w, hv.w, acc.w);
        }
        __syncthreads();
    }

    // + bias, ELU, regroup-mean (flat 4t..4t+3 -> agg[t]), GraphCON update
    float4 b = *(const float4*)(bias + tid * 4);
    float v0 = acc.x + b.x; v0 = v0 > 0.f ? v0 : expm1f(v0);
    float v1 = acc.y + b.y; v1 = v1 > 0.f ? v1 : expm1f(v1);
    float v2 = acc.z + b.z; v2 = v2 > 0.f ? v2 : expm1f(v2);
    float v3 = acc.w + b.w; v3 = v3 > 0.f ? v3 : expm1f(v3);
    float agg = 0.25f * (v0 + v1 + v2 + v3);

    size_t ofs = (size_t)d * XSTR + (size_t)l * Cc + tid;
    float xold = Xall[ofs];
    Xall[ofs + Cc] = agg;            // X_{l+1} = agg
    Yall[ofs + Cc] = agg - xold;     // Y_{l+1} = agg - X_l
}

// ---------------- classifier: out = X4 @ Wr^T + br -----------------------
__global__ __launch_bounds__(64) void logits_kernel(const float* __restrict__ Xall,
                                                    const float* __restrict__ Wr,
                                                    const float* __restrict__ br,
                                                    float* __restrict__ out)
{
    __shared__ float Xs[32 * 132];
    __shared__ float Ws[40 * 132];
    __shared__ float bs[40];
    const int tid = threadIdx.x;
    const int bmn = blockIdx.x * 32;

    for (int f = tid; f < 32 * 32; f += 64) {
        int r = f >> 5, k4 = (f & 31) << 2;
        int g = bmn + r;
        float4 v = make_float4(0.f, 0.f, 0.f, 0.f);
        if (g < Nn) v = *(const float4*)(Xall + (size_t)g * XSTR + 4 * Cc + k4);
        *(float4*)(Xs + r * 132 + k4) = v;
    }
    for (int f = tid; f < 40 * 32; f += 64) {
        int r = f >> 5, k4 = (f & 31) << 2;
        *(float4*)(Ws + r * 132 + k4) = *(const float4*)(Wr + (size_t)r * Cc + k4);
    }
    if (tid < 40) bs[tid] = br[tid];
    __syncthreads();

    const int ty = tid >> 3, tx = tid & 7;
    float acc[4][5];
    #pragma unroll
    for (int i = 0; i < 4; i++)
        #pragma unroll
        for (int j = 0; j < 5; j++) acc[i][j] = 0.f;

    #pragma unroll 4
    for (int k = 0; k < 128; k++) {
        float a[4], b[5];
        #pragma unroll
        for (int i = 0; i < 4; i++) a[i] = Xs[(ty * 4 + i) * 132 + k];
        #pragma unroll
        for (int j = 0; j < 5; j++) b[j] = Ws[(tx * 5 + j) * 132 + k];
        #pragma unroll
        for (int i = 0; i < 4; i++)
            #pragma unroll
            for (int j = 0; j < 5; j++) acc[i][j] = fmaf(a[i], b[j], acc[i][j]);
    }
    #pragma unroll
    for (int i = 0; i < 4; i++) {
        int g = bmn + ty * 4 + i;
        if (g < Nn)
            #pragma unroll
            for (int j = 0; j < 5; j++)
                out[(size_t)g * NCLS + tx * 5 + j] = acc[i][j] + bs[tx * 5 + j];
    }
}

// ---------------- launch --------------------------------------------------
extern "C" void kernel_launch(void* const* d_in, const int* in_sizes, int n_in,
                              void* d_out, int out_size)
{
    const float* x     = (const float*)d_in[0];
    const int*   src   = (const int*)  d_in[1];
    const int*   dst   = (const int*)  d_in[2];
    const float* W     = (const float*)d_in[3];
    const float* att_s = (const float*)d_in[4];
    const float* att_d = (const float*)d_in[5];
    const float* bias  = (const float*)d_in[6];
    const float* Wr    = (const float*)d_in[7];
    const float* br    = (const float*)d_in[8];

    float* out  = (float*)d_out;
    float* Xall = out + (size_t)Nn * NCLS;            // [N, 5, 128]
    float* Yall = Xall + (size_t)Nn * 5 * Cc;         // [N, 5, 128]

    cudaFuncSetAttribute(mma_gemm_kernel, cudaFuncAttributeMaxDynamicSharedMemorySize,
                         SMEM_MG);

    init_kernel<<<(Nn * Cc + 255) / 256, 256>>>(x, Xall, Yall);
    split_w_kernel<<<(Cc * Ff + 255) / 256, 256>>>(W);
    count_kernel<<<(ET + 255) / 256, 256>>>(dst);
    scan_kernel<<<1, 1024>>>();
    fill_kernel<<<(ET + 255) / 256, 256>>>(src, dst);

    for (int l = 0; l < 4; l++) {
        mma_gemm_kernel<<<157, 256, SMEM_MG>>>(Xall, l * Cc, att_s, att_d);
        edge_kernel<<<Nn, 128>>>(bias, Xall, Yall, l);
    }
    logits_kernel<<<(Nn + 31) / 32, 64>>>(Xall, Wr, br, out);
}